// round 5
// baseline (speedup 1.0000x reference)
#include <cuda_runtime.h>
#include <cstdint>

// Problem constants (fixed by the reference)
#define B_  2
#define S_  2048
#define D_  1024
#define H_  16
#define HD_ 64
#define BH  (B_*H_)          // 32
#define BSD ((long)B_*S_*D_) // 4194304

// ---------------- scratch (static device globals; no allocation) ------------
__device__ float g_wt [4u*1024u*1024u];     // transposed weights, [4][n][k]
__device__ float g_q  [BH * S_ * HD_];      // [b,h,s,hd]
__device__ float g_k  [BH * S_ * HD_];      // [b,h,s,hd]
__device__ float g_vt [BH * HD_ * S_];      // [b,h,hd,s]  (V transposed per head)
__device__ float g_ctx[B_ * S_ * D_];       // [b,s,d] merged heads

// ---------------- helpers ---------------------------------------------------
__device__ __forceinline__ uint32_t f2tf(float f) {
    uint32_t u;
    asm("cvt.rna.tf32.f32 %0, %1;" : "=r"(u) : "f"(f));
    return u;
}

// Epilogue index mapping. EPI:
// 0: head-split store   (proj Q/K)   C[((b*16+h)*2048+s)*64+hd] = v + bias[n]
// 1: head-split + T     (proj V)     C[((b*16+h)*64+hd)*2048+s] = v + bias[n]
// 2: scores             (Q@K^T)      C[z*S*S + m*S + n] = v * 0.125
// 3: ctx merge                       C[(b*2048+m)*1024 + h*64 + n] = v
// 4: plain + bias       (out proj)   C[m*1024+n] = v + bias[n]
template<int EPI>
__device__ __forceinline__ void epi_store(float* __restrict__ C,
                                          const float* __restrict__ bias,
                                          int z, int m, int n, float v)
{
    if (EPI == 0) {
        int b = m >> 11, s = m & 2047, h = n >> 6, hd = n & 63;
        C[(long)((b * 16 + h) * 2048 + s) * 64 + hd] = v + bias[n];
    } else if (EPI == 1) {
        int b = m >> 11, s = m & 2047, h = n >> 6, hd = n & 63;
        C[(long)((b * 16 + h) * 64 + hd) * 2048 + s] = v + bias[n];
    } else if (EPI == 2) {
        C[(long)z * (S_ * (long)S_) + (long)m * S_ + n] = v * 0.125f;
    } else if (EPI == 3) {
        int b = z >> 4, h = z & 15;
        C[((long)(b * 2048 + m) << 10) + h * 64 + n] = v;
    } else {
        C[(long)m * 1024 + n] = v + bias[n];
    }
}

// ---------------- generic TF32 NT GEMM --------------------------------------
// C[M,N] = A[M,K] (row-major) @ B[N,K]^T (row-major), batched by blockIdx.z.
// Tiles: 128x128x16, 256 threads (8 warps, warp tile 64x32, mma m16n8k8 tf32).
// M, K must be multiples of 128 / 16 (true for all call sites); N is guarded.
template<int EPI>
__global__ void __launch_bounds__(256, 1)
gemm_nt(const float* __restrict__ A, const float* __restrict__ Bm,
        const float* __restrict__ bias, float* __restrict__ C,
        int M, int N, int K, long sA, long sB)
{
    __shared__ float As[128 * 17];
    __shared__ float Bs[128 * 17];

    const int tid  = threadIdx.x;
    const int z    = blockIdx.z;
    const float* Ab = A  + (long)z * sA;
    const float* Bb = Bm + (long)z * sB;
    const int m0 = blockIdx.y * 128;
    const int n0 = blockIdx.x * 128;

    const int lr = tid >> 2;          // 0..63, smem-load row
    const int lc = (tid & 3) << 2;    // 0,4,8,12

    const int warp = tid >> 5;
    const int lane = tid & 31;
    const int wm  = (warp >> 2) * 64; // warp row offset in tile
    const int wn  = (warp & 3) * 32;  // warp col offset in tile
    const int gid = lane >> 2;        // mma group id (row)
    const int tig = lane & 3;         // thread-in-group (col)

    float acc[4][4][4];
    #pragma unroll
    for (int mi = 0; mi < 4; mi++)
        #pragma unroll
        for (int ni = 0; ni < 4; ni++)
            #pragma unroll
            for (int r = 0; r < 4; r++)
                acc[mi][ni][r] = 0.0f;

    for (int k0 = 0; k0 < K; k0 += 16) {
        // ---- global -> smem (tf32-rounded once here) ----
        #pragma unroll
        for (int i = 0; i < 2; i++) {
            int r = lr + i * 64;
            float4 av = *reinterpret_cast<const float4*>(
                            Ab + (long)(m0 + r) * K + (k0 + lc));
            float* as = &As[r * 17 + lc];
            as[0] = __uint_as_float(f2tf(av.x));
            as[1] = __uint_as_float(f2tf(av.y));
            as[2] = __uint_as_float(f2tf(av.z));
            as[3] = __uint_as_float(f2tf(av.w));

            float4 bv = make_float4(0.f, 0.f, 0.f, 0.f);
            if (n0 + r < N)
                bv = *reinterpret_cast<const float4*>(
                         Bb + (long)(n0 + r) * K + (k0 + lc));
            float* bs = &Bs[r * 17 + lc];
            bs[0] = __uint_as_float(f2tf(bv.x));
            bs[1] = __uint_as_float(f2tf(bv.y));
            bs[2] = __uint_as_float(f2tf(bv.z));
            bs[3] = __uint_as_float(f2tf(bv.w));
        }
        __syncthreads();

        // ---- compute: 2 k-chunks of 8 ----
        #pragma unroll
        for (int kk = 0; kk < 2; kk++) {
            const int kb = kk * 8;
            uint32_t af[4][4], bf[4][2];
            #pragma unroll
            for (int mi = 0; mi < 4; mi++) {
                int r = wm + mi * 16 + gid;
                af[mi][0] = __float_as_uint(As[ r      * 17 + kb + tig    ]);
                af[mi][1] = __float_as_uint(As[(r + 8) * 17 + kb + tig    ]);
                af[mi][2] = __float_as_uint(As[ r      * 17 + kb + tig + 4]);
                af[mi][3] = __float_as_uint(As[(r + 8) * 17 + kb + tig + 4]);
            }
            #pragma unroll
            for (int ni = 0; ni < 4; ni++) {
                int r = wn + ni * 8 + gid;
                bf[ni][0] = __float_as_uint(Bs[r * 17 + kb + tig    ]);
                bf[ni][1] = __float_as_uint(Bs[r * 17 + kb + tig + 4]);
            }
            #pragma unroll
            for (int mi = 0; mi < 4; mi++)
                #pragma unroll
                for (int ni = 0; ni < 4; ni++)
                    asm volatile(
                        "mma.sync.aligned.m16n8k8.row.col.f32.tf32.tf32.f32 "
                        "{%0,%1,%2,%3}, {%4,%5,%6,%7}, {%8,%9}, {%0,%1,%2,%3};\n"
                        : "+f"(acc[mi][ni][0]), "+f"(acc[mi][ni][1]),
                          "+f"(acc[mi][ni][2]), "+f"(acc[mi][ni][3])
                        : "r"(af[mi][0]), "r"(af[mi][1]),
                          "r"(af[mi][2]), "r"(af[mi][3]),
                          "r"(bf[ni][0]), "r"(bf[ni][1]));
        }
        __syncthreads();
    }

    // ---- epilogue ----
    #pragma unroll
    for (int mi = 0; mi < 4; mi++) {
        #pragma unroll
        for (int ni = 0; ni < 4; ni++) {
            int m = m0 + wm + mi * 16 + gid;
            int n = n0 + wn + ni * 8 + tig * 2;
            if (n < N) {
                if (m < M) {
                    epi_store<EPI>(C, bias, z, m,     n,     acc[mi][ni][0]);
                    epi_store<EPI>(C, bias, z, m,     n + 1, acc[mi][ni][1]);
                }
                if (m + 8 < M) {
                    epi_store<EPI>(C, bias, z, m + 8, n,     acc[mi][ni][2]);
                    epi_store<EPI>(C, bias, z, m + 8, n + 1, acc[mi][ni][3]);
                }
            }
        }
    }
}

// ---------------- 1024x1024 transpose (for weights) -------------------------
__global__ void __launch_bounds__(256)
transpose1024(const float* __restrict__ in, float* __restrict__ out)
{
    __shared__ float t[32][33];
    int tx = threadIdx.x, ty = threadIdx.y;
    int x  = blockIdx.x * 32 + tx;
    #pragma unroll
    for (int i = ty; i < 32; i += 8)
        t[i][tx] = in[(long)(blockIdx.y * 32 + i) * 1024 + x];
    __syncthreads();
    int xo = blockIdx.y * 32 + tx;
    #pragma unroll
    for (int i = ty; i < 32; i += 8)
        out[(long)(blockIdx.x * 32 + i) * 1024 + xo] = t[tx][i];
}

// ---------------- row softmax over 2048-wide rows, in place -----------------
__global__ void __launch_bounds__(256)
softmax_rows(float* __restrict__ attn)
{
    const long row = blockIdx.x;
    float* p = attn + row * 2048;
    const int t = threadIdx.x;

    float4 v0 = reinterpret_cast<float4*>(p)[t];
    float4 v1 = reinterpret_cast<float4*>(p)[t + 256];

    float m = fmaxf(fmaxf(fmaxf(v0.x, v0.y), fmaxf(v0.z, v0.w)),
                    fmaxf(fmaxf(v1.x, v1.y), fmaxf(v1.z, v1.w)));
    __shared__ float red[8];
    #pragma unroll
    for (int o = 16; o > 0; o >>= 1)
        m = fmaxf(m, __shfl_xor_sync(0xffffffffu, m, o));
    if ((t & 31) == 0) red[t >> 5] = m;
    __syncthreads();
    m = red[0];
    #pragma unroll
    for (int i = 1; i < 8; i++) m = fmaxf(m, red[i]);
    __syncthreads();

    v0.x = __expf(v0.x - m); v0.y = __expf(v0.y - m);
    v0.z = __expf(v0.z - m); v0.w = __expf(v0.w - m);
    v1.x = __expf(v1.x - m); v1.y = __expf(v1.y - m);
    v1.z = __expf(v1.z - m); v1.w = __expf(v1.w - m);

    float s = v0.x + v0.y + v0.z + v0.w + v1.x + v1.y + v1.z + v1.w;
    #pragma unroll
    for (int o = 16; o > 0; o >>= 1)
        s += __shfl_xor_sync(0xffffffffu, s, o);
    if ((t & 31) == 0) red[t >> 5] = s;
    __syncthreads();
    s = red[0];
    #pragma unroll
    for (int i = 1; i < 8; i++) s += red[i];

    float inv = 1.0f / s;
    v0.x *= inv; v0.y *= inv; v0.z *= inv; v0.w *= inv;
    v1.x *= inv; v1.y *= inv; v1.z *= inv; v1.w *= inv;
    reinterpret_cast<float4*>(p)[t]       = v0;
    reinterpret_cast<float4*>(p)[t + 256] = v1;
}

// ---------------- launch ----------------------------------------------------
extern "C" void kernel_launch(void* const* d_in, const int* in_sizes, int n_in,
                              void* d_out, int out_size)
{
    const float* query = (const float*)d_in[0];
    const float* key   = (const float*)d_in[1];
    const float* value = (const float*)d_in[2];
    const float* Wq    = (const float*)d_in[3];
    const float* bq    = (const float*)d_in[4];
    const float* Wk    = (const float*)d_in[5];
    const float* bk    = (const float*)d_in[6];
    const float* Wv    = (const float*)d_in[7];
    const float* bv    = (const float*)d_in[8];
    const float* Wo    = (const float*)d_in[9];
    const float* bo    = (const float*)d_in[10];

    float* out  = (float*)d_out;
    float* attn = out + BSD;   // outputs concatenated: (out, attn)

    void* p;
    cudaGetSymbolAddress(&p, g_wt);  float* wt  = (float*)p;
    cudaGetSymbolAddress(&p, g_q);   float* qh  = (float*)p;
    cudaGetSymbolAddress(&p, g_k);   float* kh  = (float*)p;
    cudaGetSymbolAddress(&p, g_vt);  float* vt  = (float*)p;
    cudaGetSymbolAddress(&p, g_ctx); float* ctx = (float*)p;

    const long WSTRIDE = 1024L * 1024L;
    dim3 tb32(32, 8);
    transpose1024<<<dim3(32, 32), tb32>>>(Wq, wt + 0 * WSTRIDE);
    transpose1024<<<dim3(32, 32), tb32>>>(Wk, wt + 1 * WSTRIDE);
    transpose1024<<<dim3(32, 32), tb32>>>(Wv, wt + 2 * WSTRIDE);
    transpose1024<<<dim3(32, 32), tb32>>>(Wo, wt + 3 * WSTRIDE);

    // Projections: [4096,1024] @ [1024,1024]^T(pre-transposed)
    gemm_nt<0><<<dim3(8, 32, 1), 256>>>(query, wt + 0 * WSTRIDE, bq, qh,
                                        4096, 1024, 1024, 0, 0);
    gemm_nt<0><<<dim3(8, 32, 1), 256>>>(key,   wt + 1 * WSTRIDE, bk, kh,
                                        4096, 1024, 1024, 0, 0);
    gemm_nt<1><<<dim3(8, 32, 1), 256>>>(value, wt + 2 * WSTRIDE, bv, vt,
                                        4096, 1024, 1024, 0, 0);

    // Scores: per (b,h): [2048,64] @ [2048,64]^T -> raw scaled scores into attn
    gemm_nt<2><<<dim3(16, 16, BH), 256>>>(qh, kh, nullptr, attn,
                                          2048, 2048, 64,
                                          (long)S_ * HD_, (long)S_ * HD_);

    // Softmax over each of B*H*S rows (in place)
    softmax_rows<<<BH * S_, 256>>>(attn);

    // ctx: per (b,h): [2048,2048] @ [64,2048]^T -> merged [B,S,D]
    gemm_nt<3><<<dim3(1, 16, BH), 256>>>(attn, vt, nullptr, ctx,
                                         2048, 64, 2048,
                                         (long)S_ * S_, (long)HD_ * S_);

    // Output projection: [4096,1024] @ [1024,1024]^T + bo
    gemm_nt<4><<<dim3(8, 32, 1), 256>>>(ctx, wt + 3 * WSTRIDE, bo, out,
                                        4096, 1024, 1024, 0, 0);
}

// round 7
// speedup vs baseline: 1.7861x; 1.7861x over previous
#include <cuda_runtime.h>
#include <cstdint>

// Problem constants (fixed by the reference)
#define B_  2
#define S_  2048
#define D_  1024
#define H_  16
#define HD_ 64
#define BH  (B_*H_)            // 32
#define BSD ((long)B_*S_*D_)   // 4194304

// ---------------- scratch (static device globals; no allocation) ------------
__device__ float g_wt  [4u*1024u*1024u];   // transposed weights [4][n][k]
__device__ float g_q   [BH * S_ * HD_];    // [b,h,s,hd]
__device__ float g_k   [BH * S_ * HD_];    // [b,h,s,hd]
__device__ float g_v   [BH * S_ * HD_];    // [b,h,s,hd]
__device__ float g_ctx [B_ * S_ * D_];     // [b,s,d]
__device__ float g_psum[BH * S_ * 16];     // per-(row, n-tile) exp partial sums
__device__ float g_inv [BH * S_];          // 1 / rowsum

// ---------------- helpers ---------------------------------------------------
__device__ __forceinline__ float f2tf(float f) {
    uint32_t u;
    asm("cvt.rna.tf32.f32 %0, %1;" : "=r"(u) : "f"(f));
    return __uint_as_float(u);
}

// ---------------- generic TF32 GEMM, 2-stage pipelined -----------------------
// C[M,N] = A[M,K] (row-major) @ B^T, batched over blockIdx.z.
//   BNN=false: B is [N,K] row-major (NT).   BNN=true: B is [K,64] row-major (NN).
//   SCA: scale A rows by inv[row] at load and write the scaled value back (attn
//        normalization fused into the ctx GEMM; each element is loaded once).
// Tiles: BMxBNx16, 256 threads, 8 warps of 64x32, mma.m16n8k8.tf32.
// All M,N,K at call sites are exact multiples of the tile dims (no guards).
// EPI: 0 head-split+bias | 2 exp(scores)+rowsums | 3 ctx merge | 4 plain+bias
template<int EPI, int BM, int BN, bool BNN, bool SCA>
__global__ void __launch_bounds__(256)
gemm(const float* __restrict__ A, const float* __restrict__ Bm,
     const float* __restrict__ bias, float* __restrict__ C,
     float* __restrict__ psum, const float* __restrict__ inv,
     int M, int N, int K, long sA, long sB)
{
    constexpr int WCOLS = BN / 32;
    constexpr int LA = BM / 64;
    constexpr int LB = (BN >= 64) ? BN / 64 : 1;

    __shared__ float As[2][BM * 17];
    __shared__ float Bs[2][BN * 17];
    __shared__ float ssum[(EPI == 2) ? BM * WCOLS : 1];

    const int tid  = threadIdx.x;
    const int z    = blockIdx.z;
    const float* Ab = A  + (long)z * sA;
    const float* Bb = Bm + (long)z * sB;
    float* Aw = const_cast<float*>(Ab);
    const int m0 = blockIdx.y * BM;
    const int n0 = blockIdx.x * BN;

    const int lr = tid >> 2;              // 0..63
    const int lc = (tid & 3) << 2;        // 0,4,8,12
    const int warp = tid >> 5;
    const int lane = tid & 31;
    const int wm  = (warp / WCOLS) * 64;
    const int wn  = (warp % WCOLS) * 32;
    const int wc  = warp % WCOLS;
    const int gid = lane >> 2;
    const int tig = lane & 3;

    float4 pa[LA];
    float4 pb[BNN ? 1 : LB];

    auto loadA = [&](int k0) {
        #pragma unroll
        for (int i = 0; i < LA; i++) {
            int r = lr + i * 64;
            float4 v = *reinterpret_cast<const float4*>(
                           Ab + (long)(m0 + r) * K + k0 + lc);
            if (SCA) {
                float s = inv[(long)z * 2048 + m0 + r];
                v.x *= s; v.y *= s; v.z *= s; v.w *= s;
                *reinterpret_cast<float4*>(
                    Aw + (long)(m0 + r) * K + k0 + lc) = v;  // normalized attn
            }
            pa[i] = v;
        }
    };
    auto loadB = [&](int k0) {
        if (BNN) {
            int kk = tid >> 4, nn = (tid & 15) << 2;
            pb[0] = *reinterpret_cast<const float4*>(
                        Bb + (long)(k0 + kk) * 64 + nn);
        } else {
            #pragma unroll
            for (int i = 0; i < LB; i++) {
                int r = lr + i * 64;
                pb[i] = *reinterpret_cast<const float4*>(
                            Bb + (long)(n0 + r) * K + k0 + lc);
            }
        }
    };
    auto sts = [&](int buf) {
        #pragma unroll
        for (int i = 0; i < LA; i++) {
            float* p = &As[buf][(lr + i * 64) * 17 + lc];
            p[0] = f2tf(pa[i].x); p[1] = f2tf(pa[i].y);
            p[2] = f2tf(pa[i].z); p[3] = f2tf(pa[i].w);
        }
        if (BNN) {
            int kk = tid >> 4, nn = (tid & 15) << 2;
            Bs[buf][(nn + 0) * 17 + kk] = f2tf(pb[0].x);
            Bs[buf][(nn + 1) * 17 + kk] = f2tf(pb[0].y);
            Bs[buf][(nn + 2) * 17 + kk] = f2tf(pb[0].z);
            Bs[buf][(nn + 3) * 17 + kk] = f2tf(pb[0].w);
        } else {
            #pragma unroll
            for (int i = 0; i < LB; i++) {
                float* p = &Bs[buf][(lr + i * 64) * 17 + lc];
                p[0] = f2tf(pb[i].x); p[1] = f2tf(pb[i].y);
                p[2] = f2tf(pb[i].z); p[3] = f2tf(pb[i].w);
            }
        }
    };

    float acc[4][4][4] = {};

    auto compute = [&](int buf) {
        #pragma unroll
        for (int kk = 0; kk < 2; kk++) {
            const int kb = kk * 8;
            uint32_t af[4][4], bf[4][2];
            #pragma unroll
            for (int mi = 0; mi < 4; mi++) {
                int r = wm + mi * 16 + gid;
                af[mi][0] = __float_as_uint(As[buf][ r      * 17 + kb + tig    ]);
                af[mi][1] = __float_as_uint(As[buf][(r + 8) * 17 + kb + tig    ]);
                af[mi][2] = __float_as_uint(As[buf][ r      * 17 + kb + tig + 4]);
                af[mi][3] = __float_as_uint(As[buf][(r + 8) * 17 + kb + tig + 4]);
            }
            #pragma unroll
            for (int ni = 0; ni < 4; ni++) {
                int r = wn + ni * 8 + gid;
                bf[ni][0] = __float_as_uint(Bs[buf][r * 17 + kb + tig    ]);
                bf[ni][1] = __float_as_uint(Bs[buf][r * 17 + kb + tig + 4]);
            }
            #pragma unroll
            for (int mi = 0; mi < 4; mi++)
                #pragma unroll
                for (int ni = 0; ni < 4; ni++)
                    asm volatile(
                        "mma.sync.aligned.m16n8k8.row.col.f32.tf32.tf32.f32 "
                        "{%0,%1,%2,%3}, {%4,%5,%6,%7}, {%8,%9}, {%0,%1,%2,%3};\n"
                        : "+f"(acc[mi][ni][0]), "+f"(acc[mi][ni][1]),
                          "+f"(acc[mi][ni][2]), "+f"(acc[mi][ni][3])
                        : "r"(af[mi][0]), "r"(af[mi][1]),
                          "r"(af[mi][2]), "r"(af[mi][3]),
                          "r"(bf[ni][0]), "r"(bf[ni][1]));
        }
    };

    // ---- 2-stage pipelined mainloop: one sync per k-tile ----
    loadA(0); loadB(0);
    sts(0);
    __syncthreads();
    int buf = 0;
    for (int k0 = 16; k0 < K; k0 += 16) {
        loadA(k0); loadB(k0);         // prefetch next tile (latency hidden)
        compute(buf);                 // MMAs on current tile
        sts(buf ^ 1);                 // stage next tile (other buffer: safe)
        buf ^= 1;
        __syncthreads();
    }
    compute(buf);

    // ---- epilogue ----
    float rs0[4] = {0, 0, 0, 0}, rs1[4] = {0, 0, 0, 0};
    #pragma unroll
    for (int mi = 0; mi < 4; mi++) {
        #pragma unroll
        for (int ni = 0; ni < 4; ni++) {
            int m = m0 + wm + mi * 16 + gid;
            int n = n0 + wn + ni * 8 + tig * 2;
            float a0 = acc[mi][ni][0], a1 = acc[mi][ni][1];
            float a2 = acc[mi][ni][2], a3 = acc[mi][ni][3];
            if constexpr (EPI == 0) {
                int b = m >> 11, s = m & 2047, h = n >> 6, hd = n & 63;
                long base = (long)((b * 16 + h) * 2048 + s) * 64 + hd;
                float b0 = bias[n], b1 = bias[n + 1];
                *(float2*)(C + base)       = make_float2(a0 + b0, a1 + b1);
                *(float2*)(C + base + 512) = make_float2(a2 + b0, a3 + b1);
            } else if constexpr (EPI == 2) {
                float e0 = __expf(a0 * 0.125f), e1 = __expf(a1 * 0.125f);
                float e2 = __expf(a2 * 0.125f), e3 = __expf(a3 * 0.125f);
                long base = (long)z * (2048L * 2048) + (long)m * 2048 + n;
                *(float2*)(C + base)            = make_float2(e0, e1);
                *(float2*)(C + base + 8 * 2048) = make_float2(e2, e3);
                rs0[mi] += e0 + e1;
                rs1[mi] += e2 + e3;
            } else if constexpr (EPI == 3) {
                int b = z >> 4, h = z & 15;
                long base = ((long)(b * 2048 + m) << 10) + h * 64 + n;
                *(float2*)(C + base)             = make_float2(a0, a1);
                *(float2*)(C + base + (8L << 10)) = make_float2(a2, a3);
            } else {
                long base = (long)m * 1024 + n;
                float b0 = bias[n], b1 = bias[n + 1];
                *(float2*)(C + base)            = make_float2(a0 + b0, a1 + b1);
                *(float2*)(C + base + 8 * 1024) = make_float2(a2 + b0, a3 + b1);
            }
        }
    }

    if constexpr (EPI == 2) {
        // deterministic per-(row, 128-wide n-tile) partial sums of exp
        #pragma unroll
        for (int mi = 0; mi < 4; mi++) {
            rs0[mi] += __shfl_xor_sync(0xffffffffu, rs0[mi], 1);
            rs0[mi] += __shfl_xor_sync(0xffffffffu, rs0[mi], 2);
            rs1[mi] += __shfl_xor_sync(0xffffffffu, rs1[mi], 1);
            rs1[mi] += __shfl_xor_sync(0xffffffffu, rs1[mi], 2);
        }
        if (tig == 0) {
            #pragma unroll
            for (int mi = 0; mi < 4; mi++) {
                ssum[(wm + mi * 16 + gid)     * WCOLS + wc] = rs0[mi];
                ssum[(wm + mi * 16 + gid + 8) * WCOLS + wc] = rs1[mi];
            }
        }
        __syncthreads();
        if (tid < BM) {
            float s = 0.0f;
            #pragma unroll
            for (int w = 0; w < WCOLS; w++) s += ssum[tid * WCOLS + w];
            psum[((long)z * 2048 + m0 + tid) * 16 + (n0 >> 7)] = s;
        }
    }
}

// ---------------- rowsum -> 1/sum -------------------------------------------
__global__ void __launch_bounds__(256)
rowsum_inv(const float* __restrict__ psum, float* __restrict__ inv)
{
    int r = blockIdx.x * 256 + threadIdx.x;   // 65536 rows
    float s = 0.0f;
    #pragma unroll
    for (int t = 0; t < 16; t++) s += psum[(long)r * 16 + t];
    inv[r] = 1.0f / s;
}

// ---------------- 1024x1024 transpose (weights) ------------------------------
__global__ void __launch_bounds__(256)
transpose1024(const float* __restrict__ in, float* __restrict__ out)
{
    __shared__ float t[32][33];
    int tx = threadIdx.x, ty = threadIdx.y;
    int x  = blockIdx.x * 32 + tx;
    #pragma unroll
    for (int i = ty; i < 32; i += 8)
        t[i][tx] = in[(long)(blockIdx.y * 32 + i) * 1024 + x];
    __syncthreads();
    int xo = blockIdx.y * 32 + tx;
    #pragma unroll
    for (int i = ty; i < 32; i += 8)
        out[(long)(blockIdx.x * 32 + i) * 1024 + xo] = t[tx][i];
}

// ---------------- launch ------------------------------------------------------
extern "C" void kernel_launch(void* const* d_in, const int* in_sizes, int n_in,
                              void* d_out, int out_size)
{
    const float* query = (const float*)d_in[0];
    const float* key   = (const float*)d_in[1];
    const float* value = (const float*)d_in[2];
    const float* Wq    = (const float*)d_in[3];
    const float* bq    = (const float*)d_in[4];
    const float* Wk    = (const float*)d_in[5];
    const float* bk    = (const float*)d_in[6];
    const float* Wv    = (const float*)d_in[7];
    const float* bv    = (const float*)d_in[8];
    const float* Wo    = (const float*)d_in[9];
    const float* bo    = (const float*)d_in[10];

    float* out  = (float*)d_out;
    float* attn = out + BSD;             // outputs concatenated: (out, attn)

    void* p;
    cudaGetSymbolAddress(&p, g_wt);   float* wt   = (float*)p;
    cudaGetSymbolAddress(&p, g_q);    float* qh   = (float*)p;
    cudaGetSymbolAddress(&p, g_k);    float* kh   = (float*)p;
    cudaGetSymbolAddress(&p, g_v);    float* vh   = (float*)p;
    cudaGetSymbolAddress(&p, g_ctx);  float* ctx  = (float*)p;
    cudaGetSymbolAddress(&p, g_psum); float* psum = (float*)p;
    cudaGetSymbolAddress(&p, g_inv);  float* vinv = (float*)p;

    const long WS = 1024L * 1024L;
    dim3 tb32(32, 8);
    transpose1024<<<dim3(32, 32), tb32>>>(Wq, wt + 0 * WS);
    transpose1024<<<dim3(32, 32), tb32>>>(Wk, wt + 1 * WS);
    transpose1024<<<dim3(32, 32), tb32>>>(Wv, wt + 2 * WS);
    transpose1024<<<dim3(32, 32), tb32>>>(Wo, wt + 3 * WS);

    // Projections (NT, head-split + bias): [4096,1024] @ W^T
    gemm<0,128,128,false,false><<<dim3(8,32,1), 256>>>(
        query, wt + 0 * WS, bq, qh, nullptr, nullptr, 4096, 1024, 1024, 0, 0);
    gemm<0,128,128,false,false><<<dim3(8,32,1), 256>>>(
        key,   wt + 1 * WS, bk, kh, nullptr, nullptr, 4096, 1024, 1024, 0, 0);
    gemm<0,128,128,false,false><<<dim3(8,32,1), 256>>>(
        value, wt + 2 * WS, bv, vh, nullptr, nullptr, 4096, 1024, 1024, 0, 0);

    // Scores (NT): per (b,h) [2048,64]@[2048,64]^T -> exp(s/8) + row partial sums
    gemm<2,128,128,false,false><<<dim3(16,16,BH), 256>>>(
        qh, kh, nullptr, attn, psum, nullptr,
        2048, 2048, 64, (long)S_ * HD_, (long)S_ * HD_);

    // 1 / rowsum
    rowsum_inv<<<256, 256>>>(psum, vinv);

    // ctx (NN, 256x64 tiles): per (b,h) [2048,2048]@[2048,64];
    // A rows scaled by inv (writes normalized attn back), heads merged into g_ctx
    gemm<3,256,64,true,true><<<dim3(1,8,BH), 256>>>(
        attn, vh, nullptr, ctx, nullptr, vinv,
        2048, 64, 2048, (long)S_ * S_, (long)S_ * HD_);

    // Output projection (NT, + bias)
    gemm<4,128,128,false,false><<<dim3(8,32,1), 256>>>(
        ctx, wt + 3 * WS, bo, out, nullptr, nullptr, 4096, 1024, 1024, 0, 0);
}

// round 8
// speedup vs baseline: 2.1610x; 1.2099x over previous
#include <cuda_runtime.h>
#include <cstdint>

// Problem constants (fixed by the reference)
#define B_  2
#define S_  2048
#define D_  1024
#define H_  16
#define HD_ 64
#define BH  (B_*H_)            // 32
#define BSD ((long)B_*S_*D_)   // 4194304

// ---------------- scratch (static device globals; no allocation) ------------
__device__ float g_wt [4u*1024u*1024u];   // transposed weights [4][n][k]
__device__ float g_q  [BH * S_ * HD_];    // [b,h,s,hd]
__device__ float g_k  [BH * S_ * HD_];    // [b,h,s,hd]
__device__ float g_v  [BH * S_ * HD_];    // [b,h,s,hd]
__device__ float g_ctx[B_ * S_ * D_];     // [b,s,d]
__device__ float g_inv[BH * S_];          // 1 / softmax rowsum

// ---------------- helpers ---------------------------------------------------
__device__ __forceinline__ float f2tf(float f) {
    uint32_t u;
    asm("cvt.rna.tf32.f32 %0, %1;" : "=r"(u) : "f"(f));
    return __uint_as_float(u);
}

#define MMA_TF32(d, a0, a1, a2, a3, b0, b1)                                   \
    asm volatile(                                                             \
        "mma.sync.aligned.m16n8k8.row.col.f32.tf32.tf32.f32 "                 \
        "{%0,%1,%2,%3}, {%4,%5,%6,%7}, {%8,%9}, {%0,%1,%2,%3};\n"             \
        : "+f"((d)[0]), "+f"((d)[1]), "+f"((d)[2]), "+f"((d)[3])              \
        : "r"(a0), "r"(a1), "r"(a2), "r"(a3), "r"(b0), "r"(b1))

// ---------------- generic TF32 NT GEMM, 2-stage pipelined --------------------
// C[M,N] = A[M,K] @ B[N,K]^T, batched over blockIdx.z. Tile 128x128x16,
// 256 threads, 8 warps of 64x32. Pad 20 -> conflict-free fragment LDS.
// EPI: 0 head-split+bias | 2 normalized-attn (exp * inv) | 4 plain+bias
template<int EPI>
__global__ void __launch_bounds__(256)
gemm_nt(const float* __restrict__ A, const float* __restrict__ Bm,
        const float* __restrict__ bias, float* __restrict__ C,
        const float* __restrict__ inv,
        int M, int N, int K, long sA, long sB)
{
    __shared__ float As[2][128 * 20];
    __shared__ float Bs[2][128 * 20];
    __shared__ float sinv[128];

    const int tid  = threadIdx.x;
    const int z    = blockIdx.z;
    const float* Ab = A  + (long)z * sA;
    const float* Bb = Bm + (long)z * sB;
    const int m0 = blockIdx.y * 128;
    const int n0 = blockIdx.x * 128;

    const int lr = tid >> 2;           // 0..63
    const int lc = (tid & 3) << 2;     // 0,4,8,12
    const int warp = tid >> 5;
    const int lane = tid & 31;
    const int wm  = (warp >> 2) * 64;
    const int wn  = (warp & 3) * 32;
    const int gid = lane >> 2;
    const int tig = lane & 3;

    float4 pa[2], pb[2];
    auto load = [&](int k0) {
        #pragma unroll
        for (int i = 0; i < 2; i++) {
            int r = lr + i * 64;
            pa[i] = *reinterpret_cast<const float4*>(Ab + (long)(m0 + r) * K + k0 + lc);
            pb[i] = *reinterpret_cast<const float4*>(Bb + (long)(n0 + r) * K + k0 + lc);
        }
    };
    auto sts = [&](int buf) {
        #pragma unroll
        for (int i = 0; i < 2; i++) {
            float* p = &As[buf][(lr + i * 64) * 20 + lc];
            p[0] = f2tf(pa[i].x); p[1] = f2tf(pa[i].y);
            p[2] = f2tf(pa[i].z); p[3] = f2tf(pa[i].w);
            float* q = &Bs[buf][(lr + i * 64) * 20 + lc];
            q[0] = f2tf(pb[i].x); q[1] = f2tf(pb[i].y);
            q[2] = f2tf(pb[i].z); q[3] = f2tf(pb[i].w);
        }
    };

    float acc[4][4][4] = {};
    auto compute = [&](int buf) {
        #pragma unroll
        for (int kk = 0; kk < 2; kk++) {
            const int kb = kk * 8;
            uint32_t af[4][4], bf[4][2];
            #pragma unroll
            for (int mi = 0; mi < 4; mi++) {
                int r = wm + mi * 16 + gid;
                af[mi][0] = __float_as_uint(As[buf][ r      * 20 + kb + tig    ]);
                af[mi][1] = __float_as_uint(As[buf][(r + 8) * 20 + kb + tig    ]);
                af[mi][2] = __float_as_uint(As[buf][ r      * 20 + kb + tig + 4]);
                af[mi][3] = __float_as_uint(As[buf][(r + 8) * 20 + kb + tig + 4]);
            }
            #pragma unroll
            for (int ni = 0; ni < 4; ni++) {
                int r = wn + ni * 8 + gid;
                bf[ni][0] = __float_as_uint(Bs[buf][r * 20 + kb + tig    ]);
                bf[ni][1] = __float_as_uint(Bs[buf][r * 20 + kb + tig + 4]);
            }
            #pragma unroll
            for (int mi = 0; mi < 4; mi++)
                #pragma unroll
                for (int ni = 0; ni < 4; ni++)
                    MMA_TF32(acc[mi][ni], af[mi][0], af[mi][1], af[mi][2],
                             af[mi][3], bf[ni][0], bf[ni][1]);
        }
    };

    load(0);
    sts(0);
    if (EPI == 2 && tid < 128)
        sinv[tid] = inv[(long)z * 2048 + m0 + tid];
    __syncthreads();
    int buf = 0;
    for (int k0 = 16; k0 < K; k0 += 16) {
        load(k0);
        compute(buf);
        sts(buf ^ 1);
        buf ^= 1;
        __syncthreads();
    }
    compute(buf);

    // ---- epilogue ----
    #pragma unroll
    for (int mi = 0; mi < 4; mi++) {
        #pragma unroll
        for (int ni = 0; ni < 4; ni++) {
            int lrow = wm + mi * 16 + gid;
            int m = m0 + lrow;
            int n = n0 + wn + ni * 8 + tig * 2;
            float a0 = acc[mi][ni][0], a1 = acc[mi][ni][1];
            float a2 = acc[mi][ni][2], a3 = acc[mi][ni][3];
            if constexpr (EPI == 0) {
                int b = m >> 11, s = m & 2047, h = n >> 6, hd = n & 63;
                long base = (long)((b * 16 + h) * 2048 + s) * 64 + hd;
                float b0 = bias[n], b1 = bias[n + 1];
                *(float2*)(C + base)       = make_float2(a0 + b0, a1 + b1);
                *(float2*)(C + base + 512) = make_float2(a2 + b0, a3 + b1);
            } else if constexpr (EPI == 2) {
                float s0 = sinv[lrow], s1 = sinv[lrow + 8];
                float e0 = __expf(a0 * 0.125f) * s0;
                float e1 = __expf(a1 * 0.125f) * s0;
                float e2 = __expf(a2 * 0.125f) * s1;
                float e3 = __expf(a3 * 0.125f) * s1;
                long base = (long)z * (2048L * 2048) + (long)m * 2048 + n;
                *(float2*)(C + base)            = make_float2(e0, e1);
                *(float2*)(C + base + 8 * 2048) = make_float2(e2, e3);
            } else {
                long base = (long)m * 1024 + n;
                float b0 = bias[n], b1 = bias[n + 1];
                *(float2*)(C + base)            = make_float2(a0 + b0, a1 + b1);
                *(float2*)(C + base + 8 * 1024) = make_float2(a2 + b0, a3 + b1);
            }
        }
    }
}

// ---------------- flash pass1: ctx + rowsum, no attn gmem traffic ------------
// Per block: one (b,h) and 128 query rows. Streams K/V in 64-key tiles:
// S = Q·K^T (tf32 mma) -> exp -> P (smem, tf32) -> ctx += P·V. Rowsums exact
// per block; ctx scaled by 1/rowsum at the end; inv written for pass2.
// 256 threads = 8 warps as 4x2 grid of 32x32 warp tiles. Pad 68 (conflict-free).
__global__ void __launch_bounds__(256)
flash_ctx(const float* __restrict__ gq, const float* __restrict__ gk,
          const float* __restrict__ gv, float* __restrict__ ctx,
          float* __restrict__ ginv)
{
    extern __shared__ float sm[];
    float* Qs   = sm;                  // 128*68
    float* Ks   = Qs + 128 * 68;       // 64*68
    float* Vs   = Ks + 64 * 68;        // 64*68  (transposed: [hd][key])
    float* Ps   = Vs + 64 * 68;        // 128*68
    float* ssum = Ps + 128 * 68;       // 128*2
    float* sinv = ssum + 256;          // 128

    const int tid  = threadIdx.x;
    const int z    = blockIdx.z;
    const int m0   = blockIdx.y * 128;
    const int warp = tid >> 5, lane = tid & 31;
    const int wm   = (warp >> 1) * 32;
    const int wn   = (warp & 1) * 32;
    const int colg = warp & 1;
    const int gid  = lane >> 2, tig = lane & 3;

    // Q tile once (reused for all 32 key-tiles)
    {
        const float* q = gq + ((long)z * 2048 + m0) * 64;
        #pragma unroll
        for (int s = 0; s < 8; s++) {
            int fi = tid + s * 256;
            int r = fi >> 4, c = (fi & 15) << 2;
            float4 v = *reinterpret_cast<const float4*>(q + r * 64 + c);
            float* p = &Qs[r * 68 + c];
            p[0] = f2tf(v.x); p[1] = f2tf(v.y);
            p[2] = f2tf(v.z); p[3] = f2tf(v.w);
        }
    }

    float acc[2][4][4] = {};           // ctx accumulator (unnormalized)
    float rsum[4] = {0.f, 0.f, 0.f, 0.f};

    for (int j = 0; j < 32; j++) {
        __syncthreads();               // prev P·V done -> Ks/Vs writable
        {
            const long base = ((long)z * 2048 + j * 64) * 64;
            #pragma unroll
            for (int s = 0; s < 4; s++) {
                int fi = tid + s * 256;
                int r = fi >> 4, c = (fi & 15) << 2;     // r=key, c=hd
                float4 kv = *reinterpret_cast<const float4*>(gk + base + r * 64 + c);
                float* p = &Ks[r * 68 + c];
                p[0] = f2tf(kv.x); p[1] = f2tf(kv.y);
                p[2] = f2tf(kv.z); p[3] = f2tf(kv.w);
                float4 vv = *reinterpret_cast<const float4*>(gv + base + r * 64 + c);
                Vs[(c + 0) * 68 + r] = f2tf(vv.x);
                Vs[(c + 1) * 68 + r] = f2tf(vv.y);
                Vs[(c + 2) * 68 + r] = f2tf(vv.z);
                Vs[(c + 3) * 68 + r] = f2tf(vv.w);
            }
        }
        __syncthreads();               // Ks/Vs ready

        // S = Q[128x64] @ K_j[64x64]^T  -> S[128q x 64key]
        float s_acc[2][4][4] = {};
        #pragma unroll
        for (int kc = 0; kc < 8; kc++) {
            const int kb = kc * 8;
            uint32_t af[2][4], bf[4][2];
            #pragma unroll
            for (int mi = 0; mi < 2; mi++) {
                int r = wm + mi * 16 + gid;
                af[mi][0] = __float_as_uint(Qs[ r      * 68 + kb + tig    ]);
                af[mi][1] = __float_as_uint(Qs[(r + 8) * 68 + kb + tig    ]);
                af[mi][2] = __float_as_uint(Qs[ r      * 68 + kb + tig + 4]);
                af[mi][3] = __float_as_uint(Qs[(r + 8) * 68 + kb + tig + 4]);
            }
            #pragma unroll
            for (int ni = 0; ni < 4; ni++) {
                int r = wn + ni * 8 + gid;
                bf[ni][0] = __float_as_uint(Ks[r * 68 + kb + tig    ]);
                bf[ni][1] = __float_as_uint(Ks[r * 68 + kb + tig + 4]);
            }
            #pragma unroll
            for (int mi = 0; mi < 2; mi++)
                #pragma unroll
                for (int ni = 0; ni < 4; ni++)
                    MMA_TF32(s_acc[mi][ni], af[mi][0], af[mi][1], af[mi][2],
                             af[mi][3], bf[ni][0], bf[ni][1]);
        }

        // exp -> P (smem tf32), accumulate rowsums
        #pragma unroll
        for (int mi = 0; mi < 2; mi++) {
            int r0 = wm + mi * 16 + gid;
            #pragma unroll
            for (int ni = 0; ni < 4; ni++) {
                int c = wn + ni * 8 + tig * 2;
                float e0 = __expf(s_acc[mi][ni][0] * 0.125f);
                float e1 = __expf(s_acc[mi][ni][1] * 0.125f);
                float e2 = __expf(s_acc[mi][ni][2] * 0.125f);
                float e3 = __expf(s_acc[mi][ni][3] * 0.125f);
                Ps[ r0      * 68 + c    ] = f2tf(e0);
                Ps[ r0      * 68 + c + 1] = f2tf(e1);
                Ps[(r0 + 8) * 68 + c    ] = f2tf(e2);
                Ps[(r0 + 8) * 68 + c + 1] = f2tf(e3);
                rsum[mi * 2 + 0] += e0 + e1;
                rsum[mi * 2 + 1] += e2 + e3;
            }
        }
        __syncthreads();               // P ready

        // ctx += P[128x64key] @ V_j (Vs is [hd][key], NT B operand)
        #pragma unroll
        for (int kc = 0; kc < 8; kc++) {
            const int kb = kc * 8;
            uint32_t af[2][4], bf[4][2];
            #pragma unroll
            for (int mi = 0; mi < 2; mi++) {
                int r = wm + mi * 16 + gid;
                af[mi][0] = __float_as_uint(Ps[ r      * 68 + kb + tig    ]);
                af[mi][1] = __float_as_uint(Ps[(r + 8) * 68 + kb + tig    ]);
                af[mi][2] = __float_as_uint(Ps[ r      * 68 + kb + tig + 4]);
                af[mi][3] = __float_as_uint(Ps[(r + 8) * 68 + kb + tig + 4]);
            }
            #pragma unroll
            for (int ni = 0; ni < 4; ni++) {
                int r = wn + ni * 8 + gid;
                bf[ni][0] = __float_as_uint(Vs[r * 68 + kb + tig    ]);
                bf[ni][1] = __float_as_uint(Vs[r * 68 + kb + tig + 4]);
            }
            #pragma unroll
            for (int mi = 0; mi < 2; mi++)
                #pragma unroll
                for (int ni = 0; ni < 4; ni++)
                    MMA_TF32(acc[mi][ni], af[mi][0], af[mi][1], af[mi][2],
                             af[mi][3], bf[ni][0], bf[ni][1]);
        }
    }

    // ---- reduce rowsums (tig quad, then warp-column halves) ----
    #pragma unroll
    for (int i = 0; i < 4; i++) {
        rsum[i] += __shfl_xor_sync(0xffffffffu, rsum[i], 1);
        rsum[i] += __shfl_xor_sync(0xffffffffu, rsum[i], 2);
    }
    if (tig == 0) {
        #pragma unroll
        for (int i = 0; i < 4; i++) {
            int r = wm + (i >> 1) * 16 + gid + (i & 1) * 8;
            ssum[r * 2 + colg] = rsum[i];
        }
    }
    __syncthreads();
    if (tid < 128) {
        float v = 1.0f / (ssum[tid * 2] + ssum[tid * 2 + 1]);
        sinv[tid] = v;
        ginv[(long)z * 2048 + m0 + tid] = v;
    }
    __syncthreads();

    // ---- write normalized ctx, heads merged ----
    const int b = z >> 4, h = z & 15;
    #pragma unroll
    for (int mi = 0; mi < 2; mi++) {
        int r0 = wm + mi * 16 + gid;
        float s0 = sinv[r0], s1 = sinv[r0 + 8];
        #pragma unroll
        for (int ni = 0; ni < 4; ni++) {
            int c = wn + ni * 8 + tig * 2;
            long base = ((long)(b * 2048 + m0 + r0) << 10) + h * 64 + c;
            *(float2*)(ctx + base) =
                make_float2(acc[mi][ni][0] * s0, acc[mi][ni][1] * s0);
            *(float2*)(ctx + base + (8L << 10)) =
                make_float2(acc[mi][ni][2] * s1, acc[mi][ni][3] * s1);
        }
    }
}

// ---------------- 1024x1024 transpose (weights) ------------------------------
__global__ void __launch_bounds__(256)
transpose1024(const float* __restrict__ in, float* __restrict__ out)
{
    __shared__ float t[32][33];
    int tx = threadIdx.x, ty = threadIdx.y;
    int x  = blockIdx.x * 32 + tx;
    #pragma unroll
    for (int i = ty; i < 32; i += 8)
        t[i][tx] = in[(long)(blockIdx.y * 32 + i) * 1024 + x];
    __syncthreads();
    int xo = blockIdx.y * 32 + tx;
    #pragma unroll
    for (int i = ty; i < 32; i += 8)
        out[(long)(blockIdx.x * 32 + i) * 1024 + xo] = t[tx][i];
}

// ---------------- launch ------------------------------------------------------
extern "C" void kernel_launch(void* const* d_in, const int* in_sizes, int n_in,
                              void* d_out, int out_size)
{
    const float* query = (const float*)d_in[0];
    const float* key   = (const float*)d_in[1];
    const float* value = (const float*)d_in[2];
    const float* Wq    = (const float*)d_in[3];
    const float* bq    = (const float*)d_in[4];
    const float* Wk    = (const float*)d_in[5];
    const float* bk    = (const float*)d_in[6];
    const float* Wv    = (const float*)d_in[7];
    const float* bv    = (const float*)d_in[8];
    const float* Wo    = (const float*)d_in[9];
    const float* bo    = (const float*)d_in[10];

    float* out  = (float*)d_out;
    float* attn = out + BSD;             // outputs concatenated: (out, attn)

    void* p;
    cudaGetSymbolAddress(&p, g_wt);  float* wt   = (float*)p;
    cudaGetSymbolAddress(&p, g_q);   float* qh   = (float*)p;
    cudaGetSymbolAddress(&p, g_k);   float* kh   = (float*)p;
    cudaGetSymbolAddress(&p, g_v);   float* vh   = (float*)p;
    cudaGetSymbolAddress(&p, g_ctx); float* ctx  = (float*)p;
    cudaGetSymbolAddress(&p, g_inv); float* vinv = (float*)p;

    static int smem_set = 0;
    const int FLASH_SMEM = (128*68 + 64*68 + 64*68 + 128*68 + 256 + 128) * 4;
    if (!smem_set) {
        cudaFuncSetAttribute(flash_ctx,
                             cudaFuncAttributeMaxDynamicSharedMemorySize,
                             FLASH_SMEM);
        smem_set = 1;
    }

    const long WS = 1024L * 1024L;
    dim3 tb32(32, 8);
    transpose1024<<<dim3(32, 32), tb32>>>(Wq, wt + 0 * WS);
    transpose1024<<<dim3(32, 32), tb32>>>(Wk, wt + 1 * WS);
    transpose1024<<<dim3(32, 32), tb32>>>(Wv, wt + 2 * WS);
    transpose1024<<<dim3(32, 32), tb32>>>(Wo, wt + 3 * WS);

    // Projections (NT, head-split + bias): [4096,1024] @ W^T
    gemm_nt<0><<<dim3(8, 32, 1), 256>>>(query, wt + 0 * WS, bq, qh, nullptr,
                                        4096, 1024, 1024, 0, 0);
    gemm_nt<0><<<dim3(8, 32, 1), 256>>>(key,   wt + 1 * WS, bk, kh, nullptr,
                                        4096, 1024, 1024, 0, 0);
    gemm_nt<0><<<dim3(8, 32, 1), 256>>>(value, wt + 2 * WS, bv, vh, nullptr,
                                        4096, 1024, 1024, 0, 0);

    // pass1: fused scores->softmax-sum->ctx, no attn traffic; writes ctx + inv
    flash_ctx<<<dim3(1, 16, BH), 256, FLASH_SMEM>>>(qh, kh, vh, ctx, vinv);

    // pass2: recompute scores, write normalized attn once (required output)
    gemm_nt<2><<<dim3(16, 16, BH), 256>>>(qh, kh, nullptr, attn, vinv,
                                          2048, 2048, 64,
                                          (long)S_ * HD_, (long)S_ * HD_);

    // Output projection (NT, + bias)
    gemm_nt<4><<<dim3(8, 32, 1), 256>>>(ctx, wt + 3 * WS, bo, out, nullptr,
                                        4096, 1024, 1024, 0, 0);
}

// round 9
// speedup vs baseline: 2.1740x; 1.0060x over previous
#include <cuda_runtime.h>
#include <cstdint>

// Problem constants (fixed by the reference)
#define B_  2
#define S_  2048
#define D_  1024
#define H_  16
#define HD_ 64
#define BH  (B_*H_)            // 32
#define BSD ((long)B_*S_*D_)   // 4194304

// ---------------- scratch (static device globals; no allocation) ------------
__device__ float g_wt [4u*1024u*1024u];   // transposed weights [4][n][k]
__device__ float g_q  [BH * S_ * HD_];    // [b,h,s,hd]
__device__ float g_k  [BH * S_ * HD_];    // [b,h,s,hd]
__device__ float g_v  [BH * S_ * HD_];    // [b,h,s,hd]
__device__ float g_ctx[B_ * S_ * D_];     // [b,s,d]
__device__ float g_inv[BH * S_];          // 1 / softmax rowsum

// ---------------- helpers ---------------------------------------------------
__device__ __forceinline__ float f2tf(float f) {
    uint32_t u;
    asm("cvt.rna.tf32.f32 %0, %1;" : "=r"(u) : "f"(f));
    return __uint_as_float(u);
}

#define MMA_TF32(d, a0, a1, a2, a3, b0, b1)                                   \
    asm volatile(                                                             \
        "mma.sync.aligned.m16n8k8.row.col.f32.tf32.tf32.f32 "                 \
        "{%0,%1,%2,%3}, {%4,%5,%6,%7}, {%8,%9}, {%0,%1,%2,%3};\n"             \
        : "+f"((d)[0]), "+f"((d)[1]), "+f"((d)[2]), "+f"((d)[3])              \
        : "r"(a0), "r"(a1), "r"(a2), "r"(a3), "r"(b0), "r"(b1))

// ---------------- shared TF32 NT GEMM body (2-stage pipelined) ---------------
// C[M,N] = A[M,K] @ B[N,K]^T for one 128x128 tile at (m0, n0).
// 256 threads, 8 warps of 64x32, pad 20 (conflict-free fragment LDS).
// EPI: 0 head-split+bias | 2 normalized attn (exp*inv, streaming store)
//    | 4 plain+bias
// smem layout (floats): As[2][2560] | Bs[2][2560] | sinv[128]
constexpr int GEMM_SMF = 4 * 128 * 20 + 128;

template<int EPI>
__device__ __forceinline__ void gemm_body(
    float* sm_, const float* __restrict__ Ab, const float* __restrict__ Bb,
    const float* __restrict__ bias, float* __restrict__ C,
    const float* __restrict__ inv, int z, int m0, int n0, int K)
{
    float* As0 = sm_;
    float* Bs0 = sm_ + 2 * 128 * 20;
    float* sinv = sm_ + 4 * 128 * 20;

    const int tid  = threadIdx.x;
    const int lr = tid >> 2;           // 0..63
    const int lc = (tid & 3) << 2;     // 0,4,8,12
    const int warp = tid >> 5;
    const int lane = tid & 31;
    const int wm  = (warp >> 2) * 64;
    const int wn  = (warp & 3) * 32;
    const int gid = lane >> 2;
    const int tig = lane & 3;

    float4 pa[2], pb[2];
    auto load = [&](int k0) {
        #pragma unroll
        for (int i = 0; i < 2; i++) {
            int r = lr + i * 64;
            pa[i] = *reinterpret_cast<const float4*>(Ab + (long)(m0 + r) * K + k0 + lc);
            pb[i] = *reinterpret_cast<const float4*>(Bb + (long)(n0 + r) * K + k0 + lc);
        }
    };
    auto sts = [&](int buf) {
        float* Asb = As0 + buf * (128 * 20);
        float* Bsb = Bs0 + buf * (128 * 20);
        #pragma unroll
        for (int i = 0; i < 2; i++) {
            float* p = &Asb[(lr + i * 64) * 20 + lc];
            p[0] = f2tf(pa[i].x); p[1] = f2tf(pa[i].y);
            p[2] = f2tf(pa[i].z); p[3] = f2tf(pa[i].w);
            float* q = &Bsb[(lr + i * 64) * 20 + lc];
            q[0] = f2tf(pb[i].x); q[1] = f2tf(pb[i].y);
            q[2] = f2tf(pb[i].z); q[3] = f2tf(pb[i].w);
        }
    };

    float acc[4][4][4] = {};
    auto compute = [&](int buf) {
        float* Asb = As0 + buf * (128 * 20);
        float* Bsb = Bs0 + buf * (128 * 20);
        #pragma unroll
        for (int kk = 0; kk < 2; kk++) {
            const int kb = kk * 8;
            uint32_t af[4][4], bf[4][2];
            #pragma unroll
            for (int mi = 0; mi < 4; mi++) {
                int r = wm + mi * 16 + gid;
                af[mi][0] = __float_as_uint(Asb[ r      * 20 + kb + tig    ]);
                af[mi][1] = __float_as_uint(Asb[(r + 8) * 20 + kb + tig    ]);
                af[mi][2] = __float_as_uint(Asb[ r      * 20 + kb + tig + 4]);
                af[mi][3] = __float_as_uint(Asb[(r + 8) * 20 + kb + tig + 4]);
            }
            #pragma unroll
            for (int ni = 0; ni < 4; ni++) {
                int r = wn + ni * 8 + gid;
                bf[ni][0] = __float_as_uint(Bsb[r * 20 + kb + tig    ]);
                bf[ni][1] = __float_as_uint(Bsb[r * 20 + kb + tig + 4]);
            }
            #pragma unroll
            for (int mi = 0; mi < 4; mi++)
                #pragma unroll
                for (int ni = 0; ni < 4; ni++)
                    MMA_TF32(acc[mi][ni], af[mi][0], af[mi][1], af[mi][2],
                             af[mi][3], bf[ni][0], bf[ni][1]);
        }
    };

    load(0);
    sts(0);
    if (EPI == 2 && tid < 128)
        sinv[tid] = inv[(long)z * 2048 + m0 + tid];
    __syncthreads();
    int buf = 0;
    for (int k0 = 16; k0 < K; k0 += 16) {
        load(k0);
        compute(buf);
        sts(buf ^ 1);
        buf ^= 1;
        __syncthreads();
    }
    compute(buf);

    // ---- epilogue ----
    #pragma unroll
    for (int mi = 0; mi < 4; mi++) {
        #pragma unroll
        for (int ni = 0; ni < 4; ni++) {
            int lrow = wm + mi * 16 + gid;
            int m = m0 + lrow;
            int n = n0 + wn + ni * 8 + tig * 2;
            float a0 = acc[mi][ni][0], a1 = acc[mi][ni][1];
            float a2 = acc[mi][ni][2], a3 = acc[mi][ni][3];
            if constexpr (EPI == 0) {
                int b = m >> 11, s = m & 2047, h = n >> 6, hd = n & 63;
                long base = (long)((b * 16 + h) * 2048 + s) * 64 + hd;
                float b0 = bias[n], b1 = bias[n + 1];
                *(float2*)(C + base)       = make_float2(a0 + b0, a1 + b1);
                *(float2*)(C + base + 512) = make_float2(a2 + b0, a3 + b1);
            } else if constexpr (EPI == 2) {
                float s0 = sinv[lrow], s1 = sinv[lrow + 8];
                float e0 = __expf(a0 * 0.125f) * s0;
                float e1 = __expf(a1 * 0.125f) * s0;
                float e2 = __expf(a2 * 0.125f) * s1;
                float e3 = __expf(a3 * 0.125f) * s1;
                long base = (long)z * (2048L * 2048) + (long)m * 2048 + n;
                __stcs((float2*)(C + base),            make_float2(e0, e1));
                __stcs((float2*)(C + base + 8 * 2048), make_float2(e2, e3));
            } else {
                long base = (long)m * 1024 + n;
                float b0 = bias[n], b1 = bias[n + 1];
                *(float2*)(C + base)            = make_float2(a0 + b0, a1 + b1);
                *(float2*)(C + base + 8 * 1024) = make_float2(a2 + b0, a3 + b1);
            }
        }
    }
}

// ---------------- fused Q/K/V projection (one launch, grid.z selects) --------
__global__ void __launch_bounds__(256)
qkv_proj(const float* __restrict__ q, const float* __restrict__ k,
         const float* __restrict__ v, const float* __restrict__ wt,
         const float* __restrict__ bq, const float* __restrict__ bk,
         const float* __restrict__ bv,
         float* __restrict__ gq, float* __restrict__ gk, float* __restrict__ gv)
{
    __shared__ float sm_[GEMM_SMF];
    const int z = blockIdx.z;
    const float* A    = (z == 0) ? q  : (z == 1) ? k  : v;
    const float* bias = (z == 0) ? bq : (z == 1) ? bk : bv;
    float*       C    = (z == 0) ? gq : (z == 1) ? gk : gv;
    gemm_body<0>(sm_, A, wt + (long)z * 1024 * 1024, bias, C, nullptr, 0,
                 blockIdx.y * 128, blockIdx.x * 128, 1024);
}

// ---------------- merged pass2 (attn write) + output projection --------------
// bid [0,256): out projection tiles (scheduled first -> fills wave 1)
// bid [256, 256+8192): normalized-attn tiles
__global__ void __launch_bounds__(256)
attn_out_combo(const float* __restrict__ qh, const float* __restrict__ kh,
               const float* __restrict__ vinv, float* __restrict__ attn,
               const float* __restrict__ ctx, const float* __restrict__ wo_t,
               const float* __restrict__ bo, float* __restrict__ out)
{
    __shared__ float sm_[GEMM_SMF];
    const int bid = blockIdx.x;
    if (bid < 256) {
        int m0 = (bid >> 3) * 128;     // 32 m-tiles
        int n0 = (bid & 7) * 128;      // 8 n-tiles
        gemm_body<4>(sm_, ctx, wo_t, bo, out, nullptr, 0, m0, n0, 1024);
    } else {
        int t  = bid - 256;
        int z  = t >> 8;               // 32 heads*batch
        int m0 = ((t >> 4) & 15) * 128;
        int n0 = (t & 15) * 128;
        gemm_body<2>(sm_, qh + (long)z * S_ * HD_, kh + (long)z * S_ * HD_,
                     nullptr, attn, vinv, z, m0, n0, 64);
    }
}

// ---------------- flash pass1: ctx + rowsum, K/V double-buffered -------------
// Per block: one (b,h), 128 query rows. 64-key tiles; prefetch next K/V into
// registers during S-MMA, stage into alternate smem buffer mid-iteration.
// 2 barriers/iteration. 8 warps as 4x2 grid of 32x32 warp tiles. Pad 68.
__global__ void __launch_bounds__(256)
flash_ctx(const float* __restrict__ gq, const float* __restrict__ gk,
          const float* __restrict__ gv, float* __restrict__ ctx,
          float* __restrict__ ginv)
{
    extern __shared__ float sm[];
    float* Qs   = sm;                   // 128*68            = 8704
    float* Ks   = Qs + 128 * 68;        // 2 stages * 64*68  = 8704
    float* Vs   = Ks + 2 * 64 * 68;     // 2 stages * 64*68  = 8704 ([hd][key])
    float* Ps   = Vs + 2 * 64 * 68;     // 128*68            = 8704
    float* ssum = Ps + 128 * 68;        // 256
    float* sinv = ssum + 256;           // 128

    const int tid  = threadIdx.x;
    const int z    = blockIdx.z;
    const int m0   = blockIdx.y * 128;
    const int warp = tid >> 5, lane = tid & 31;
    const int wm   = (warp >> 1) * 32;
    const int wn   = (warp & 1) * 32;
    const int colg = warp & 1;
    const int gid  = lane >> 2, tig = lane & 3;

    // Q tile once (reused for all 32 key-tiles)
    {
        const float* q = gq + ((long)z * 2048 + m0) * 64;
        #pragma unroll
        for (int s = 0; s < 8; s++) {
            int fi = tid + s * 256;
            int r = fi >> 4, c = (fi & 15) << 2;
            float4 v = *reinterpret_cast<const float4*>(q + r * 64 + c);
            float* p = &Qs[r * 68 + c];
            p[0] = f2tf(v.x); p[1] = f2tf(v.y);
            p[2] = f2tf(v.z); p[3] = f2tf(v.w);
        }
    }

    float4 pk[4], pv[4];
    auto ldg_kv = [&](int j) {
        const long base = ((long)z * 2048 + j * 64) * 64;
        #pragma unroll
        for (int s = 0; s < 4; s++) {
            int fi = tid + s * 256;
            int r = fi >> 4, c = (fi & 15) << 2;
            pk[s] = *reinterpret_cast<const float4*>(gk + base + r * 64 + c);
            pv[s] = *reinterpret_cast<const float4*>(gv + base + r * 64 + c);
        }
    };
    auto sts_kv = [&](int b) {
        float* Ksb = Ks + b * (64 * 68);
        float* Vsb = Vs + b * (64 * 68);
        #pragma unroll
        for (int s = 0; s < 4; s++) {
            int fi = tid + s * 256;
            int r = fi >> 4, c = (fi & 15) << 2;    // r=key, c=hd
            float* p = &Ksb[r * 68 + c];
            p[0] = f2tf(pk[s].x); p[1] = f2tf(pk[s].y);
            p[2] = f2tf(pk[s].z); p[3] = f2tf(pk[s].w);
            Vsb[(c + 0) * 68 + r] = f2tf(pv[s].x);
            Vsb[(c + 1) * 68 + r] = f2tf(pv[s].y);
            Vsb[(c + 2) * 68 + r] = f2tf(pv[s].z);
            Vsb[(c + 3) * 68 + r] = f2tf(pv[s].w);
        }
    };

    float acc[2][4][4] = {};            // ctx accumulator (unnormalized)
    float rsum[4] = {0.f, 0.f, 0.f, 0.f};

    ldg_kv(0);
    sts_kv(0);
    __syncthreads();
    int buf = 0;

    for (int j = 0; j < 32; j++) {
        if (j < 31) ldg_kv(j + 1);      // prefetch; latency hidden under S-MMA

        // S = Q[128x64] @ K_j[64x64]^T
        float* Ksb = Ks + buf * (64 * 68);
        float s_acc[2][4][4] = {};
        #pragma unroll
        for (int kc = 0; kc < 8; kc++) {
            const int kb = kc * 8;
            uint32_t af[2][4], bf[4][2];
            #pragma unroll
            for (int mi = 0; mi < 2; mi++) {
                int r = wm + mi * 16 + gid;
                af[mi][0] = __float_as_uint(Qs[ r      * 68 + kb + tig    ]);
                af[mi][1] = __float_as_uint(Qs[(r + 8) * 68 + kb + tig    ]);
                af[mi][2] = __float_as_uint(Qs[ r      * 68 + kb + tig + 4]);
                af[mi][3] = __float_as_uint(Qs[(r + 8) * 68 + kb + tig + 4]);
            }
            #pragma unroll
            for (int ni = 0; ni < 4; ni++) {
                int r = wn + ni * 8 + gid;
                bf[ni][0] = __float_as_uint(Ksb[r * 68 + kb + tig    ]);
                bf[ni][1] = __float_as_uint(Ksb[r * 68 + kb + tig + 4]);
            }
            #pragma unroll
            for (int mi = 0; mi < 2; mi++)
                #pragma unroll
                for (int ni = 0; ni < 4; ni++)
                    MMA_TF32(s_acc[mi][ni], af[mi][0], af[mi][1], af[mi][2],
                             af[mi][3], bf[ni][0], bf[ni][1]);
        }

        // exp -> P (smem tf32), accumulate rowsums
        #pragma unroll
        for (int mi = 0; mi < 2; mi++) {
            int r0 = wm + mi * 16 + gid;
            #pragma unroll
            for (int ni = 0; ni < 4; ni++) {
                int c = wn + ni * 8 + tig * 2;
                float e0 = __expf(s_acc[mi][ni][0] * 0.125f);
                float e1 = __expf(s_acc[mi][ni][1] * 0.125f);
                float e2 = __expf(s_acc[mi][ni][2] * 0.125f);
                float e3 = __expf(s_acc[mi][ni][3] * 0.125f);
                Ps[ r0      * 68 + c    ] = f2tf(e0);
                Ps[ r0      * 68 + c + 1] = f2tf(e1);
                Ps[(r0 + 8) * 68 + c    ] = f2tf(e2);
                Ps[(r0 + 8) * 68 + c + 1] = f2tf(e3);
                rsum[mi * 2 + 0] += e0 + e1;
                rsum[mi * 2 + 1] += e2 + e3;
            }
        }
        __syncthreads();   // Ps ready; all warps past iter j-1's reads of buf^1

        if (j < 31) sts_kv(buf ^ 1);    // stage next tile into idle buffer

        // ctx += P[128x64] @ V_j   (Vs is [hd][key] -> NT B operand)
        float* Vsb = Vs + buf * (64 * 68);
        #pragma unroll
        for (int kc = 0; kc < 8; kc++) {
            const int kb = kc * 8;
            uint32_t af[2][4], bf[4][2];
            #pragma unroll
            for (int mi = 0; mi < 2; mi++) {
                int r = wm + mi * 16 + gid;
                af[mi][0] = __float_as_uint(Ps[ r      * 68 + kb + tig    ]);
                af[mi][1] = __float_as_uint(Ps[(r + 8) * 68 + kb + tig    ]);
                af[mi][2] = __float_as_uint(Ps[ r      * 68 + kb + tig + 4]);
                af[mi][3] = __float_as_uint(Ps[(r + 8) * 68 + kb + tig + 4]);
            }
            #pragma unroll
            for (int ni = 0; ni < 4; ni++) {
                int r = wn + ni * 8 + gid;
                bf[ni][0] = __float_as_uint(Vsb[r * 68 + kb + tig    ]);
                bf[ni][1] = __float_as_uint(Vsb[r * 68 + kb + tig + 4]);
            }
            #pragma unroll
            for (int mi = 0; mi < 2; mi++)
                #pragma unroll
                for (int ni = 0; ni < 4; ni++)
                    MMA_TF32(acc[mi][ni], af[mi][0], af[mi][1], af[mi][2],
                             af[mi][3], bf[ni][0], bf[ni][1]);
        }
        __syncthreads();   // next buffer fully staged; Ps free for overwrite
        buf ^= 1;
    }

    // ---- reduce rowsums ----
    #pragma unroll
    for (int i = 0; i < 4; i++) {
        rsum[i] += __shfl_xor_sync(0xffffffffu, rsum[i], 1);
        rsum[i] += __shfl_xor_sync(0xffffffffu, rsum[i], 2);
    }
    if (tig == 0) {
        #pragma unroll
        for (int i = 0; i < 4; i++) {
            int r = wm + (i >> 1) * 16 + gid + (i & 1) * 8;
            ssum[r * 2 + colg] = rsum[i];
        }
    }
    __syncthreads();
    if (tid < 128) {
        float v = 1.0f / (ssum[tid * 2] + ssum[tid * 2 + 1]);
        sinv[tid] = v;
        ginv[(long)z * 2048 + m0 + tid] = v;
    }
    __syncthreads();

    // ---- write normalized ctx, heads merged ----
    const int b = z >> 4, h = z & 15;
    #pragma unroll
    for (int mi = 0; mi < 2; mi++) {
        int r0 = wm + mi * 16 + gid;
        float s0 = sinv[r0], s1 = sinv[r0 + 8];
        #pragma unroll
        for (int ni = 0; ni < 4; ni++) {
            int c = wn + ni * 8 + tig * 2;
            long base = ((long)(b * 2048 + m0 + r0) << 10) + h * 64 + c;
            *(float2*)(ctx + base) =
                make_float2(acc[mi][ni][0] * s0, acc[mi][ni][1] * s0);
            *(float2*)(ctx + base + (8L << 10)) =
                make_float2(acc[mi][ni][2] * s1, acc[mi][ni][3] * s1);
        }
    }
}

// ---------------- fused 4x 1024x1024 weight transpose ------------------------
__global__ void __launch_bounds__(256)
transpose4(const float* __restrict__ w0, const float* __restrict__ w1,
           const float* __restrict__ w2, const float* __restrict__ w3,
           float* __restrict__ out)
{
    __shared__ float t[32][33];
    const int z = blockIdx.z;
    const float* in = (z == 0) ? w0 : (z == 1) ? w1 : (z == 2) ? w2 : w3;
    float* o = out + (long)z * 1024 * 1024;
    int tx = threadIdx.x, ty = threadIdx.y;
    int x  = blockIdx.x * 32 + tx;
    #pragma unroll
    for (int i = ty; i < 32; i += 8)
        t[i][tx] = in[(long)(blockIdx.y * 32 + i) * 1024 + x];
    __syncthreads();
    int xo = blockIdx.y * 32 + tx;
    #pragma unroll
    for (int i = ty; i < 32; i += 8)
        o[(long)(blockIdx.x * 32 + i) * 1024 + xo] = t[tx][i];
}

// ---------------- launch ------------------------------------------------------
extern "C" void kernel_launch(void* const* d_in, const int* in_sizes, int n_in,
                              void* d_out, int out_size)
{
    const float* query = (const float*)d_in[0];
    const float* key   = (const float*)d_in[1];
    const float* value = (const float*)d_in[2];
    const float* Wq    = (const float*)d_in[3];
    const float* bq    = (const float*)d_in[4];
    const float* Wk    = (const float*)d_in[5];
    const float* bk    = (const float*)d_in[6];
    const float* Wv    = (const float*)d_in[7];
    const float* bv    = (const float*)d_in[8];
    const float* Wo    = (const float*)d_in[9];
    const float* bo    = (const float*)d_in[10];

    float* out  = (float*)d_out;
    float* attn = out + BSD;             // outputs concatenated: (out, attn)

    void* p;
    cudaGetSymbolAddress(&p, g_wt);  float* wt   = (float*)p;
    cudaGetSymbolAddress(&p, g_q);   float* qh   = (float*)p;
    cudaGetSymbolAddress(&p, g_k);   float* kh   = (float*)p;
    cudaGetSymbolAddress(&p, g_v);   float* vh   = (float*)p;
    cudaGetSymbolAddress(&p, g_ctx); float* ctx  = (float*)p;
    cudaGetSymbolAddress(&p, g_inv); float* vinv = (float*)p;

    const int FLASH_SMEM =
        (128*68 + 2*64*68 + 2*64*68 + 128*68 + 256 + 128) * 4;  // ~141 KB
    static int smem_set = 0;
    if (!smem_set) {
        cudaFuncSetAttribute(flash_ctx,
                             cudaFuncAttributeMaxDynamicSharedMemorySize,
                             FLASH_SMEM);
        smem_set = 1;
    }

    const long WS = 1024L * 1024L;

    // 1) all four weight transposes in one launch
    transpose4<<<dim3(32, 32, 4), dim3(32, 8)>>>(Wq, Wk, Wv, Wo, wt);

    // 2) fused Q/K/V projections (768 blocks, one launch)
    qkv_proj<<<dim3(8, 32, 3), 256>>>(query, key, value, wt,
                                      bq, bk, bv, qh, kh, vh);

    // 3) fused scores->softmax-sum->ctx (no attn gmem traffic); writes ctx+inv
    flash_ctx<<<dim3(1, 16, BH), 256, FLASH_SMEM>>>(qh, kh, vh, ctx, vinv);

    // 4) merged: out-projection (256 blocks, first) + normalized attn write
    attn_out_combo<<<256 + 8192, 256>>>(qh, kh, vinv, attn,
                                        ctx, wt + 3 * WS, bo, out);
}